// round 14
// baseline (speedup 1.0000x reference)
#include <cuda_runtime.h>
#include <cuda_fp16.h>
#include <cstdint>

#define N_NODES 50000
#define N_RELS  8
#define IN_DIM  128
#define OUT_DIM 128
#define N_EDGES 800000
#define M_TILES ((N_NODES + 127) / 128)   // 391

// Scratch (__device__ globals: allocation-free rule)
__device__ __align__(16) __half g_h[(size_t)N_RELS * N_NODES * OUT_DIM]; // 102.4 MB fp16
__device__ float g_counts[N_RELS * N_NODES];                             // 1.6 MB
__device__ __align__(16) __half g_wt[N_RELS * 128 * 128];                // W^T fp16 [r][o][k]

// ---------------------------------------------------------------------------
// helpers (baseline PTX ISA — safe for plain sm_103 ptx target)
// ---------------------------------------------------------------------------
__device__ __forceinline__ uint32_t smem_u32(const void* p) {
    uint32_t a;
    asm("{ .reg .u64 t; cvta.to.shared.u64 t, %1; cvt.u32.u64 %0, t; }"
        : "=r"(a) : "l"(p));
    return a;
}

__device__ __forceinline__ void ldsm4(uint32_t* r, uint32_t addr) {
    asm volatile("ldmatrix.sync.aligned.m8n8.x4.shared.b16 {%0,%1,%2,%3}, [%4];"
                 : "=r"(r[0]), "=r"(r[1]), "=r"(r[2]), "=r"(r[3]) : "r"(addr));
}

__device__ __forceinline__ void mma_fp16(float* d, const uint32_t* a, const uint32_t* b) {
    asm volatile(
        "mma.sync.aligned.m16n8k16.row.col.f32.f16.f16.f32 "
        "{%0,%1,%2,%3}, {%4,%5,%6,%7}, {%8,%9}, {%0,%1,%2,%3};"
        : "+f"(d[0]), "+f"(d[1]), "+f"(d[2]), "+f"(d[3])
        : "r"(a[0]), "r"(a[1]), "r"(a[2]), "r"(a[3]), "r"(b[0]), "r"(b[1]));
}

// tile row = 256B (128 fp16) = 16 chunks of 16B; chunk' = chunk ^ (row&7)
__device__ __forceinline__ uint32_t sw_off(int row, int chunk) {
    return (uint32_t)(row * 256 + ((chunk ^ (row & 7)) << 4));
}

// SMEM: A 32KB | B 32KB = 64KB
#define SM_A 0
#define SM_B 32768
#define SMEM_TOTAL 65536

// ---------------------------------------------------------------------------
// Kernel 1: out = bias, counts = 0
// ---------------------------------------------------------------------------
__global__ void init_kernel(float* __restrict__ out, const float* __restrict__ bias) {
    int idx = blockIdx.x * blockDim.x + threadIdx.x;
    int stride = gridDim.x * blockDim.x;
    const int total = N_NODES * OUT_DIM;
    for (int i = idx; i < total; i += stride)
        out[i] = bias[i & (OUT_DIM - 1)];
    for (int i = idx; i < N_RELS * N_NODES; i += stride)
        g_counts[i] = 0.0f;
}

// ---------------------------------------------------------------------------
// Kernel 2: counts[rel*N + tgt] += 1
// ---------------------------------------------------------------------------
__global__ void count_kernel(const int* __restrict__ triples) {
    int e = blockIdx.x * blockDim.x + threadIdx.x;
    if (e < N_EDGES) {
        int rel = triples[e * 3 + 1];
        int tgt = triples[e * 3 + 2];
        atomicAdd(&g_counts[rel * N_NODES + tgt], 1.0f);
    }
}

// ---------------------------------------------------------------------------
// Kernel 2b: W [r][k][o] fp32 -> Wt fp16 [r][o][k] (transpose + convert)
// ---------------------------------------------------------------------------
__global__ void split_w_kernel(const float* __restrict__ W) {
    int idx = blockIdx.x * blockDim.x + threadIdx.x;
    if (idx >= N_RELS * 128 * 128) return;
    int r = idx >> 14;
    int k = (idx >> 7) & 127;
    int o = idx & 127;
    g_wt[(r << 14) + (o << 7) + k] = __float2half_rn(W[idx]);
}

// ---------------------------------------------------------------------------
// Kernel 3: fp16 GEMM via mma.sync: h[r] = fp16(features) @ fp16(W[r])
//   CTA = 128x128 tile for one relation (r = blockIdx.y + r_base),
//   512 threads (16 warps, 32x32/warp). Output h stored fp16.
// ---------------------------------------------------------------------------
__global__ void __launch_bounds__(512, 1)
gemm_mma_kernel(const float* __restrict__ A, int r_base) {
    extern __shared__ char smem[];
    const int r  = blockIdx.y + r_base;
    const int m0 = blockIdx.x * 128;
    const int tid = threadIdx.x;
    const int wid = tid >> 5;
    const int lid = tid & 31;
    const uint32_t sb = smem_u32(smem);

    // ---- fill smem: A (convert fp32->fp16) and B (pre-converted fp16) ----
    {
        const __half* B = g_wt + (r << 14);
#pragma unroll
        for (int i = 0; i < 4; i++) {
            int cid = tid + i * 512;          // 2048 chunks
            int row = cid >> 4;
            int chunk = cid & 15;
            uint32_t so = sw_off(row, chunk);

            *(uint4*)(smem + SM_B + so) = *(const uint4*)(B + (row << 7) + (chunk << 3));

            int grow = m0 + row;
            if (grow >= N_NODES) grow = 0;    // junk rows; epilogue guards
            const float* p = A + ((size_t)grow << 7) + (chunk << 3);
            float4 x0 = *(const float4*)p;
            float4 x1 = *(const float4*)(p + 4);
            uint32_t pk[4];
            __half2 h0 = __floats2half2_rn(x0.x, x0.y);
            __half2 h1 = __floats2half2_rn(x0.z, x0.w);
            __half2 h2 = __floats2half2_rn(x1.x, x1.y);
            __half2 h3 = __floats2half2_rn(x1.z, x1.w);
            pk[0] = *reinterpret_cast<uint32_t*>(&h0);
            pk[1] = *reinterpret_cast<uint32_t*>(&h1);
            pk[2] = *reinterpret_cast<uint32_t*>(&h2);
            pk[3] = *reinterpret_cast<uint32_t*>(&h3);
            *(uint4*)(smem + SM_A + so) = make_uint4(pk[0], pk[1], pk[2], pk[3]);
        }
    }
    __syncthreads();

    // ---- per-lane ldmatrix addresses (warp = 32m x 32n) ----
    const int wm = wid & 3;          // 4 m-tiles of 32 rows
    const int wn = wid >> 2;         // 4 n-tiles of 32 cols
    const int a_row = wm * 32 + (lid & 15);
    const int a_kc  = lid >> 4;
    const int a_and = a_row & 7;
    const uint32_t a_base = sb + (uint32_t)(a_row * 256);
    const int b_row = wn * 32 + ((lid >> 4) << 3) + (lid & 7);
    const int b_kc  = (lid >> 3) & 1;
    const int b_and = b_row & 7;     // invariant under +16
    const uint32_t b_base = sb + (uint32_t)(b_row * 256);

    float acc[2][4][4];
#pragma unroll
    for (int mt = 0; mt < 2; mt++)
#pragma unroll
        for (int nn = 0; nn < 4; nn++)
#pragma unroll
            for (int c = 0; c < 4; c++) acc[mt][nn][c] = 0.0f;

#pragma unroll
    for (int s = 0; s < 8; s++) {
        uint32_t Ah[2][4], Bh4[2][4];
        const uint32_t ac = (uint32_t)(((s * 2 + a_kc) ^ a_and) << 4);
        const uint32_t bc = (uint32_t)(((s * 2 + b_kc) ^ b_and) << 4);
#pragma unroll
        for (int t2 = 0; t2 < 2; t2++) {
            ldsm4(Ah[t2], a_base + SM_A + t2 * 4096 + ac);
            ldsm4(Bh4[t2], b_base + SM_B + t2 * 4096 + bc);
        }
#pragma unroll
        for (int g = 0; g < 2; g++) {
#pragma unroll
            for (int half = 0; half < 2; half++) {
                const int nn = g * 2 + half;
                const uint32_t* bh = &Bh4[g][half * 2];
#pragma unroll
                for (int mt = 0; mt < 2; mt++)
                    mma_fp16(acc[mt][nn], Ah[mt], bh);
            }
        }
    }

    // ---- epilogue: write fp16 h[r] tile ----
    __half* H = g_h + ((size_t)r * N_NODES << 7);
    const int col0 = wn * 32 + (lid & 3) * 2;
    const int row_lo = m0 + wm * 32 + (lid >> 2);
#pragma unroll
    for (int mt = 0; mt < 2; mt++) {
        int row = row_lo + mt * 16;
        if (row < N_NODES) {
            __half* Hp = H + ((size_t)row << 7) + col0;
#pragma unroll
            for (int nn = 0; nn < 4; nn++) {
                __half2 hv = __floats2half2_rn(acc[mt][nn][0], acc[mt][nn][1]);
                *(uint32_t*)(Hp + nn * 8) = *reinterpret_cast<uint32_t*>(&hv);
            }
        }
        if (row + 8 < N_NODES) {
            __half* Hp = H + ((size_t)(row + 8) << 7) + col0;
#pragma unroll
            for (int nn = 0; nn < 4; nn++) {
                __half2 hv = __floats2half2_rn(acc[mt][nn][2], acc[mt][nn][3]);
                *(uint32_t*)(Hp + nn * 8) = *reinterpret_cast<uint32_t*>(&hv);
            }
        }
    }
}

// ---------------------------------------------------------------------------
// Kernel 4: edge pass over rel range [r_lo, r_hi). 2 edges/thread, 8 lanes/edge.
//   h loads predicated on range so each pass touches only its 51.2MB h slice
//   (L2-resident together with out + triples).
// ---------------------------------------------------------------------------
__global__ void edge_kernel(const int* __restrict__ triples, float* __restrict__ out,
                            int r_lo, int r_hi) {
    int t = blockIdx.x * blockDim.x + threadIdx.x;
    int gi = t >> 3;            // edge-pair index
    int p = t & 7;              // 32B segment within fp16 row
    int e0 = gi * 2;
    if (e0 >= N_EDGES) return;
    int e1 = e0 + 1;
    bool has1 = (e1 < N_EDGES);

    int s0 = triples[e0 * 3 + 0];
    int r0 = triples[e0 * 3 + 1];
    int t0 = triples[e0 * 3 + 2];
    int s1 = has1 ? triples[e1 * 3 + 0] : s0;
    int r1 = has1 ? triples[e1 * 3 + 1] : r0;
    int t1 = has1 ? triples[e1 * 3 + 2] : t0;

    bool do0 = (r0 >= r_lo) && (r0 < r_hi);
    bool do1 = has1 && (r1 >= r_lo) && (r1 < r_hi);
    if (!do0 && !do1) return;

    float val0 = do0 ? 1.0f / g_counts[r0 * N_NODES + t0] : 0.0f;
    float val1 = do1 ? 1.0f / g_counts[r1 * N_NODES + t1] : 0.0f;

    // issue gathers up front (predicated)
    uint4 A0 = {0,0,0,0}, A1 = {0,0,0,0}, B0 = {0,0,0,0}, B1 = {0,0,0,0};
    if (do0) {
        const uint4* ha = (const uint4*)(g_h + (((size_t)r0 * N_NODES + s0) << 7)) + p * 2;
        A0 = ha[0]; A1 = ha[1];
    }
    if (do1) {
        const uint4* hb = (const uint4*)(g_h + (((size_t)r1 * N_NODES + s1) << 7)) + p * 2;
        B0 = hb[0]; B1 = hb[1];
    }

    if (do0) {
        float4* o0 = (float4*)(out + ((size_t)t0 << 7)) + p * 4;
#pragma unroll
        for (int q = 0; q < 4; q++) {
            uint32_t lo = (q < 2) ? ((q == 0) ? A0.x : A0.z) : ((q == 2) ? A1.x : A1.z);
            uint32_t hi = (q < 2) ? ((q == 0) ? A0.y : A0.w) : ((q == 2) ? A1.y : A1.w);
            float2 fa = __half22float2(*reinterpret_cast<__half2*>(&lo));
            float2 fb = __half22float2(*reinterpret_cast<__half2*>(&hi));
            asm volatile("red.global.add.v4.f32 [%0], {%1, %2, %3, %4};"
                         :: "l"(o0 + q),
                            "f"(fa.x * val0), "f"(fa.y * val0),
                            "f"(fb.x * val0), "f"(fb.y * val0) : "memory");
        }
    }
    if (do1) {
        float4* o1 = (float4*)(out + ((size_t)t1 << 7)) + p * 4;
#pragma unroll
        for (int q = 0; q < 4; q++) {
            uint32_t lo = (q < 2) ? ((q == 0) ? B0.x : B0.z) : ((q == 2) ? B1.x : B1.z);
            uint32_t hi = (q < 2) ? ((q == 0) ? B0.y : B0.w) : ((q == 2) ? B1.y : B1.w);
            float2 fa = __half22float2(*reinterpret_cast<__half2*>(&lo));
            float2 fb = __half22float2(*reinterpret_cast<__half2*>(&hi));
            asm volatile("red.global.add.v4.f32 [%0], {%1, %2, %3, %4};"
                         :: "l"(o1 + q),
                            "f"(fa.x * val1), "f"(fa.y * val1),
                            "f"(fb.x * val1), "f"(fb.y * val1) : "memory");
        }
    }
}

// ---------------------------------------------------------------------------
extern "C" void kernel_launch(void* const* d_in, const int* in_sizes, int n_in,
                              void* d_out, int out_size) {
    const int*   triples  = (const int*)d_in[0];    // [E, 3] (src, rel, tgt)
    const float* features = (const float*)d_in[1];  // [N, 128]
    const float* weights  = (const float*)d_in[2];  // [8, 128, 128]
    const float* bias     = (const float*)d_in[3];  // [128]
    float* out = (float*)d_out;                     // [N, 128]
    (void)in_sizes; (void)n_in; (void)out_size;

    cudaFuncSetAttribute(gemm_mma_kernel,
                         cudaFuncAttributeMaxDynamicSharedMemorySize, SMEM_TOTAL);

    init_kernel<<<1024, 256>>>(out, bias);
    count_kernel<<<(N_EDGES + 255) / 256, 256>>>(triples);
    split_w_kernel<<<(N_RELS * 128 * 128 + 255) / 256, 256>>>(weights);

    // Producer/consumer ordering for L2 residency:
    // write h[4..8) first, then h[0..4) (hot in L2) -> consume h[0..4) -> h[4..8)
    dim3 gg(M_TILES, 4);
    gemm_mma_kernel<<<gg, 512, SMEM_TOTAL>>>(features, 4);
    gemm_mma_kernel<<<gg, 512, SMEM_TOTAL>>>(features, 0);

    int nthreads = (N_EDGES + 1) / 2 * 8;
    edge_kernel<<<(nthreads + 511) / 512, 512>>>(triples, out, 0, 4);
    edge_kernel<<<(nthreads + 511) / 512, 512>>>(triples, out, 4, 8);
}

// round 15
// speedup vs baseline: 1.0517x; 1.0517x over previous
#include <cuda_runtime.h>
#include <cuda_fp16.h>
#include <cstdint>

#define N_NODES 50000
#define N_RELS  8
#define IN_DIM  128
#define OUT_DIM 128
#define N_EDGES 800000
#define M_TILES ((N_NODES + 127) / 128)   // 391

// Scratch (__device__ globals: allocation-free rule)
__device__ __align__(16) __half g_h[(size_t)N_RELS * N_NODES * OUT_DIM]; // 102.4 MB fp16
__device__ float g_counts[N_RELS * N_NODES];                             // 1.6 MB
__device__ __align__(16) __half g_wt[N_RELS * 128 * 128];                // W^T fp16 [r][o][k]
__device__ __align__(16) __half g_af[(size_t)N_NODES * IN_DIM];          // features fp16 (12.8 MB)

// ---------------------------------------------------------------------------
// helpers (baseline PTX ISA — safe for plain sm_103 ptx target)
// ---------------------------------------------------------------------------
__device__ __forceinline__ uint32_t smem_u32(const void* p) {
    uint32_t a;
    asm("{ .reg .u64 t; cvta.to.shared.u64 t, %1; cvt.u32.u64 %0, t; }"
        : "=r"(a) : "l"(p));
    return a;
}

__device__ __forceinline__ void ldsm4(uint32_t* r, uint32_t addr) {
    asm volatile("ldmatrix.sync.aligned.m8n8.x4.shared.b16 {%0,%1,%2,%3}, [%4];"
                 : "=r"(r[0]), "=r"(r[1]), "=r"(r[2]), "=r"(r[3]) : "r"(addr));
}

__device__ __forceinline__ void mma_fp16(float* d, const uint32_t* a, const uint32_t* b) {
    asm volatile(
        "mma.sync.aligned.m16n8k16.row.col.f32.f16.f16.f32 "
        "{%0,%1,%2,%3}, {%4,%5,%6,%7}, {%8,%9}, {%0,%1,%2,%3};"
        : "+f"(d[0]), "+f"(d[1]), "+f"(d[2]), "+f"(d[3])
        : "r"(a[0]), "r"(a[1]), "r"(a[2]), "r"(a[3]), "r"(b[0]), "r"(b[1]));
}

// tile row = 256B (128 fp16) = 16 chunks of 16B; chunk' = chunk ^ (row&7)
__device__ __forceinline__ uint32_t sw_off(int row, int chunk) {
    return (uint32_t)(row * 256 + ((chunk ^ (row & 7)) << 4));
}

// SMEM: A 32KB | B 32KB = 64KB
#define SM_A 0
#define SM_B 32768
#define SMEM_TOTAL 65536

// ---------------------------------------------------------------------------
// Kernel 1: out = bias, counts = 0
// ---------------------------------------------------------------------------
__global__ void init_kernel(float* __restrict__ out, const float* __restrict__ bias) {
    int idx = blockIdx.x * blockDim.x + threadIdx.x;
    int stride = gridDim.x * blockDim.x;
    const int total = N_NODES * OUT_DIM;
    for (int i = idx; i < total; i += stride)
        out[i] = bias[i & (OUT_DIM - 1)];
    for (int i = idx; i < N_RELS * N_NODES; i += stride)
        g_counts[i] = 0.0f;
}

// ---------------------------------------------------------------------------
// Kernel 2: counts[rel*N + tgt] += 1
// ---------------------------------------------------------------------------
__global__ void count_kernel(const int* __restrict__ triples) {
    int e = blockIdx.x * blockDim.x + threadIdx.x;
    if (e < N_EDGES) {
        int rel = triples[e * 3 + 1];
        int tgt = triples[e * 3 + 2];
        atomicAdd(&g_counts[rel * N_NODES + tgt], 1.0f);
    }
}

// ---------------------------------------------------------------------------
// Kernel 2b: W [r][k][o] fp32 -> Wt fp16 [r][o][k] (transpose + convert)
// ---------------------------------------------------------------------------
__global__ void split_w_kernel(const float* __restrict__ W) {
    int idx = blockIdx.x * blockDim.x + threadIdx.x;
    if (idx >= N_RELS * 128 * 128) return;
    int r = idx >> 14;
    int k = (idx >> 7) & 127;
    int o = idx & 127;
    g_wt[(r << 14) + (o << 7) + k] = __float2half_rn(W[idx]);
}

// ---------------------------------------------------------------------------
// Kernel 2c: features fp32 -> fp16 (once; GEMM fill becomes pure copies)
// ---------------------------------------------------------------------------
__global__ void conv_a_kernel(const float* __restrict__ A) {
    int idx = blockIdx.x * blockDim.x + threadIdx.x;   // one per 8 elements
    const int n8 = N_NODES * IN_DIM / 8;
    if (idx >= n8) return;
    const float4* p = (const float4*)A + idx * 2;
    float4 x0 = p[0];
    float4 x1 = p[1];
    __half2 h0 = __floats2half2_rn(x0.x, x0.y);
    __half2 h1 = __floats2half2_rn(x0.z, x0.w);
    __half2 h2 = __floats2half2_rn(x1.x, x1.y);
    __half2 h3 = __floats2half2_rn(x1.z, x1.w);
    uint4 v = make_uint4(*reinterpret_cast<uint32_t*>(&h0),
                         *reinterpret_cast<uint32_t*>(&h1),
                         *reinterpret_cast<uint32_t*>(&h2),
                         *reinterpret_cast<uint32_t*>(&h3));
    *((uint4*)g_af + idx) = v;
}

// ---------------------------------------------------------------------------
// Kernel 3: fp16 GEMM via mma.sync: h[r] = fp16(features) @ fp16(W[r])
//   CTA = 128x128 tile for one relation, 512 threads (16 warps, 32x32/warp).
//   Fill is pure uint4 copies (A pre-converted). Output h stored fp16.
// ---------------------------------------------------------------------------
__global__ void __launch_bounds__(512, 1)
gemm_mma_kernel() {
    extern __shared__ char smem[];
    const int r  = blockIdx.y;
    const int m0 = blockIdx.x * 128;
    const int tid = threadIdx.x;
    const int wid = tid >> 5;
    const int lid = tid & 31;
    const uint32_t sb = smem_u32(smem);

    // ---- fill smem: A and B, both pre-converted fp16 (pure copies) ----
    {
        const __half* B = g_wt + (r << 14);
#pragma unroll
        for (int i = 0; i < 4; i++) {
            int cid = tid + i * 512;          // 2048 chunks
            int row = cid >> 4;
            int chunk = cid & 15;
            uint32_t so = sw_off(row, chunk);

            *(uint4*)(smem + SM_B + so) = *(const uint4*)(B + (row << 7) + (chunk << 3));

            int grow = m0 + row;
            if (grow >= N_NODES) grow = 0;    // junk rows; epilogue guards
            *(uint4*)(smem + SM_A + so) =
                *(const uint4*)(g_af + ((size_t)grow << 7) + (chunk << 3));
        }
    }
    __syncthreads();

    // ---- per-lane ldmatrix addresses (warp = 32m x 32n) ----
    const int wm = wid & 3;          // 4 m-tiles of 32 rows
    const int wn = wid >> 2;         // 4 n-tiles of 32 cols
    const int a_row = wm * 32 + (lid & 15);
    const int a_kc  = lid >> 4;
    const int a_and = a_row & 7;
    const uint32_t a_base = sb + (uint32_t)(a_row * 256);
    const int b_row = wn * 32 + ((lid >> 4) << 3) + (lid & 7);
    const int b_kc  = (lid >> 3) & 1;
    const int b_and = b_row & 7;     // invariant under +16
    const uint32_t b_base = sb + (uint32_t)(b_row * 256);

    float acc[2][4][4];
#pragma unroll
    for (int mt = 0; mt < 2; mt++)
#pragma unroll
        for (int nn = 0; nn < 4; nn++)
#pragma unroll
            for (int c = 0; c < 4; c++) acc[mt][nn][c] = 0.0f;

#pragma unroll
    for (int s = 0; s < 8; s++) {
        uint32_t Ah[2][4], Bh4[2][4];
        const uint32_t ac = (uint32_t)(((s * 2 + a_kc) ^ a_and) << 4);
        const uint32_t bc = (uint32_t)(((s * 2 + b_kc) ^ b_and) << 4);
#pragma unroll
        for (int t2 = 0; t2 < 2; t2++) {
            ldsm4(Ah[t2], a_base + SM_A + t2 * 4096 + ac);
            ldsm4(Bh4[t2], b_base + SM_B + t2 * 4096 + bc);
        }
#pragma unroll
        for (int g = 0; g < 2; g++) {
#pragma unroll
            for (int half = 0; half < 2; half++) {
                const int nn = g * 2 + half;
                const uint32_t* bh = &Bh4[g][half * 2];
#pragma unroll
                for (int mt = 0; mt < 2; mt++)
                    mma_fp16(acc[mt][nn], Ah[mt], bh);
            }
        }
    }

    // ---- epilogue: write fp16 h[r] tile ----
    __half* H = g_h + ((size_t)r * N_NODES << 7);
    const int col0 = wn * 32 + (lid & 3) * 2;
    const int row_lo = m0 + wm * 32 + (lid >> 2);
#pragma unroll
    for (int mt = 0; mt < 2; mt++) {
        int row = row_lo + mt * 16;
        if (row < N_NODES) {
            __half* Hp = H + ((size_t)row << 7) + col0;
#pragma unroll
            for (int nn = 0; nn < 4; nn++) {
                __half2 hv = __floats2half2_rn(acc[mt][nn][0], acc[mt][nn][1]);
                *(uint32_t*)(Hp + nn * 8) = *reinterpret_cast<uint32_t*>(&hv);
            }
        }
        if (row + 8 < N_NODES) {
            __half* Hp = H + ((size_t)(row + 8) << 7) + col0;
#pragma unroll
            for (int nn = 0; nn < 4; nn++) {
                __half2 hv = __floats2half2_rn(acc[mt][nn][2], acc[mt][nn][3]);
                *(uint32_t*)(Hp + nn * 8) = *reinterpret_cast<uint32_t*>(&hv);
            }
        }
    }
}

// ---------------------------------------------------------------------------
// Kernel 4: 4 edges per thread, 8 lanes/edge slot; h rows fp16 (256B).
//   All 8 independent uint4 gathers issued before any RED (MLP=8).
//   out[tgt] += h[rel,src] / counts[rel*N+tgt]   (fp32 RED)
// ---------------------------------------------------------------------------
__global__ void edge_kernel(const int* __restrict__ triples, float* __restrict__ out) {
    int t = blockIdx.x * blockDim.x + threadIdx.x;
    int gi = t >> 3;            // edge-quad index
    int p = t & 7;              // 32B segment within fp16 row
    int e0 = gi * 4;
    if (e0 >= N_EDGES) return;  // N_EDGES % 4 == 0, quads are full

    int s[4], rl[4], tg[4];
#pragma unroll
    for (int j = 0; j < 4; j++) {
        int e = e0 + j;
        s[j]  = triples[e * 3 + 0];
        rl[j] = triples[e * 3 + 1];
        tg[j] = triples[e * 3 + 2];
    }

    float val[4];
#pragma unroll
    for (int j = 0; j < 4; j++)
        val[j] = 1.0f / g_counts[rl[j] * N_NODES + tg[j]];

    // issue all 8 gathers up front
    uint4 L[4][2];
#pragma unroll
    for (int j = 0; j < 4; j++) {
        const uint4* h = (const uint4*)(g_h + (((size_t)rl[j] * N_NODES + s[j]) << 7)) + p * 2;
        L[j][0] = h[0];
        L[j][1] = h[1];
    }

#pragma unroll
    for (int j = 0; j < 4; j++) {
        float4* o = (float4*)(out + ((size_t)tg[j] << 7)) + p * 4;
        float v = val[j];
#pragma unroll
        for (int q = 0; q < 4; q++) {
            uint32_t lo = (q < 2) ? ((q == 0) ? L[j][0].x : L[j][0].z)
                                  : ((q == 2) ? L[j][1].x : L[j][1].z);
            uint32_t hi = (q < 2) ? ((q == 0) ? L[j][0].y : L[j][0].w)
                                  : ((q == 2) ? L[j][1].y : L[j][1].w);
            float2 fa = __half22float2(*reinterpret_cast<__half2*>(&lo));
            float2 fb = __half22float2(*reinterpret_cast<__half2*>(&hi));
            asm volatile("red.global.add.v4.f32 [%0], {%1, %2, %3, %4};"
                         :: "l"(o + q),
                            "f"(fa.x * v), "f"(fa.y * v),
                            "f"(fb.x * v), "f"(fb.y * v) : "memory");
        }
    }
}

// ---------------------------------------------------------------------------
extern "C" void kernel_launch(void* const* d_in, const int* in_sizes, int n_in,
                              void* d_out, int out_size) {
    const int*   triples  = (const int*)d_in[0];    // [E, 3] (src, rel, tgt)
    const float* features = (const float*)d_in[1];  // [N, 128]
    const float* weights  = (const float*)d_in[2];  // [8, 128, 128]
    const float* bias     = (const float*)d_in[3];  // [128]
    float* out = (float*)d_out;                     // [N, 128]
    (void)in_sizes; (void)n_in; (void)out_size;

    cudaFuncSetAttribute(gemm_mma_kernel,
                         cudaFuncAttributeMaxDynamicSharedMemorySize, SMEM_TOTAL);

    init_kernel<<<1024, 256>>>(out, bias);
    count_kernel<<<(N_EDGES + 255) / 256, 256>>>(triples);
    split_w_kernel<<<(N_RELS * 128 * 128 + 255) / 256, 256>>>(weights);
    conv_a_kernel<<<(N_NODES * IN_DIM / 8 + 255) / 256, 256>>>(features);

    dim3 gg(M_TILES, N_RELS);
    gemm_mma_kernel<<<gg, 512, SMEM_TOTAL>>>();

    // 4 edges per thread, 8 threads per edge-quad
    edge_kernel<<<(N_EDGES / 4 * 8 + 511) / 512, 512>>>(triples, out);
}

// round 17
// speedup vs baseline: 1.4056x; 1.3365x over previous
#include <cuda_runtime.h>
#include <cuda_fp16.h>
#include <cstdint>

#define N_NODES 50000
#define N_RELS  8
#define IN_DIM  128
#define OUT_DIM 128
#define N_EDGES 800000
#define MT      64
#define M_TILES ((N_NODES + MT - 1) / MT)   // 782

// Scratch (__device__ globals: allocation-free rule)
__device__ __align__(16) __half g_agg[(size_t)N_RELS * N_NODES * IN_DIM]; // 102.4 MB fp16
__device__ float g_counts[N_RELS * N_NODES];                              // 1.6 MB
__device__ __align__(16) __half g_wt[N_RELS * 128 * 128];                 // W^T fp16 [r][o][k]
__device__ __align__(16) __half g_af[(size_t)N_NODES * IN_DIM];           // features fp16 (12.8 MB)

// ---------------------------------------------------------------------------
// helpers (baseline PTX ISA — safe for plain sm_103 ptx target)
// ---------------------------------------------------------------------------
__device__ __forceinline__ uint32_t smem_u32(const void* p) {
    uint32_t a;
    asm("{ .reg .u64 t; cvta.to.shared.u64 t, %1; cvt.u32.u64 %0, t; }"
        : "=r"(a) : "l"(p));
    return a;
}

__device__ __forceinline__ void ldsm4(uint32_t* r, uint32_t addr) {
    asm volatile("ldmatrix.sync.aligned.m8n8.x4.shared.b16 {%0,%1,%2,%3}, [%4];"
                 : "=r"(r[0]), "=r"(r[1]), "=r"(r[2]), "=r"(r[3]) : "r"(addr));
}

__device__ __forceinline__ void mma_fp16(float* d, const uint32_t* a, const uint32_t* b) {
    asm volatile(
        "mma.sync.aligned.m16n8k16.row.col.f32.f16.f16.f32 "
        "{%0,%1,%2,%3}, {%4,%5,%6,%7}, {%8,%9}, {%0,%1,%2,%3};"
        : "+f"(d[0]), "+f"(d[1]), "+f"(d[2]), "+f"(d[3])
        : "r"(a[0]), "r"(a[1]), "r"(a[2]), "r"(a[3]), "r"(b[0]), "r"(b[1]));
}

__device__ __forceinline__ void cp16(uint32_t dst, const void* src) {
    asm volatile("cp.async.ca.shared.global [%0], [%1], 16;"
                 :: "r"(dst), "l"(src) : "memory");
}
#define CP_COMMIT() asm volatile("cp.async.commit_group;" ::: "memory")
#define CP_WAIT(n)  asm volatile("cp.async.wait_group %0;" :: "n"(n) : "memory")

// tile row = 256B (128 fp16) = 16 chunks of 16B; chunk' = chunk ^ (row&7)
__device__ __forceinline__ uint32_t sw_off(int row, int chunk) {
    return (uint32_t)(row * 256 + ((chunk ^ (row & 7)) << 4));
}

// SMEM: A 16KB | Bbuf0 32KB | Bbuf1 32KB = 80KB
#define SM_A 0
#define SM_B 16384            // + buf*32768
#define SMEM_TOTAL 81920

// ---------------------------------------------------------------------------
// Kernel 1: agg = 0, counts = 0
// ---------------------------------------------------------------------------
__global__ void init_kernel() {
    int idx = blockIdx.x * blockDim.x + threadIdx.x;
    int stride = gridDim.x * blockDim.x;
    uint4* a4 = (uint4*)g_agg;
    const int n4 = (int)(((size_t)N_RELS * N_NODES * IN_DIM) >> 3);  // halves/8
    uint4 z = make_uint4(0, 0, 0, 0);
    for (int i = idx; i < n4; i += stride) a4[i] = z;
    for (int i = idx; i < N_RELS * N_NODES; i += stride) g_counts[i] = 0.0f;
}

// ---------------------------------------------------------------------------
// Kernel 2: counts[rel*N + tgt] += 1
// ---------------------------------------------------------------------------
__global__ void count_kernel(const int* __restrict__ triples) {
    int e = blockIdx.x * blockDim.x + threadIdx.x;
    if (e < N_EDGES) {
        int rel = triples[e * 3 + 1];
        int tgt = triples[e * 3 + 2];
        atomicAdd(&g_counts[rel * N_NODES + tgt], 1.0f);
    }
}

// ---------------------------------------------------------------------------
// Kernel 2b: W [r][k][o] fp32 -> Wt fp16 [r][o][k] (transpose + convert)
// ---------------------------------------------------------------------------
__global__ void split_w_kernel(const float* __restrict__ W) {
    int idx = blockIdx.x * blockDim.x + threadIdx.x;
    if (idx >= N_RELS * 128 * 128) return;
    int r = idx >> 14;
    int k = (idx >> 7) & 127;
    int o = idx & 127;
    g_wt[(r << 14) + (o << 7) + k] = __float2half_rn(W[idx]);
}

// ---------------------------------------------------------------------------
// Kernel 2c: features fp32 -> fp16
// ---------------------------------------------------------------------------
__global__ void conv_a_kernel(const float* __restrict__ A) {
    int idx = blockIdx.x * blockDim.x + threadIdx.x;   // one per 8 elements
    const int n8 = N_NODES * IN_DIM / 8;
    if (idx >= n8) return;
    const float4* p = (const float4*)A + idx * 2;
    float4 x0 = p[0];
    float4 x1 = p[1];
    __half2 h0 = __floats2half2_rn(x0.x, x0.y);
    __half2 h1 = __floats2half2_rn(x0.z, x0.w);
    __half2 h2 = __floats2half2_rn(x1.x, x1.y);
    __half2 h3 = __floats2half2_rn(x1.z, x1.w);
    uint4 v = make_uint4(*reinterpret_cast<uint32_t*>(&h0),
                         *reinterpret_cast<uint32_t*>(&h1),
                         *reinterpret_cast<uint32_t*>(&h2),
                         *reinterpret_cast<uint32_t*>(&h3));
    *((uint4*)g_af + idx) = v;
}

// ---------------------------------------------------------------------------
// Kernel 3: scatter  agg[rel,tgt] += fp16(features[src] * val)
//   4 edges/thread, 8 lanes/edge (32B segment). Gathers from L2-resident
//   g_af; REDs are v4.f16x2 (16B), 2 per edge-lane.
// ---------------------------------------------------------------------------
__global__ void scatter_kernel(const int* __restrict__ triples) {
    int t = blockIdx.x * blockDim.x + threadIdx.x;
    int gi = t >> 3;            // edge-quad index
    int p = t & 7;              // 32B segment within fp16 row
    int e0 = gi * 4;
    if (e0 >= N_EDGES) return;  // N_EDGES % 4 == 0

    int s[4], rl[4], tg[4];
#pragma unroll
    for (int j = 0; j < 4; j++) {
        int e = e0 + j;
        s[j]  = triples[e * 3 + 0];
        rl[j] = triples[e * 3 + 1];
        tg[j] = triples[e * 3 + 2];
    }

    float val[4];
#pragma unroll
    for (int j = 0; j < 4; j++)
        val[j] = 1.0f / g_counts[rl[j] * N_NODES + tg[j]];

    // issue all 8 gathers up front (L2-resident g_af)
    uint4 F[4][2];
#pragma unroll
    for (int j = 0; j < 4; j++) {
        const uint4* f = (const uint4*)(g_af + ((size_t)s[j] << 7)) + p * 2;
        F[j][0] = f[0];
        F[j][1] = f[1];
    }

#pragma unroll
    for (int j = 0; j < 4; j++) {
        uint4* d = (uint4*)(g_agg + (((size_t)rl[j] * N_NODES + tg[j]) << 7)) + p * 2;
        float v = val[j];
#pragma unroll
        for (int h = 0; h < 2; h++) {
            uint32_t w[4] = {F[j][h].x, F[j][h].y, F[j][h].z, F[j][h].w};
            uint32_t m[4];
#pragma unroll
            for (int q = 0; q < 4; q++) {
                float2 f2 = __half22float2(*reinterpret_cast<__half2*>(&w[q]));
                __half2 hv = __floats2half2_rn(f2.x * v, f2.y * v);
                m[q] = *reinterpret_cast<uint32_t*>(&hv);
            }
            asm volatile("red.global.add.noftz.v4.f16x2 [%0], {%1, %2, %3, %4};"
                         :: "l"(d + h), "r"(m[0]), "r"(m[1]), "r"(m[2]), "r"(m[3])
                         : "memory");
        }
    }
}

// ---------------------------------------------------------------------------
// Kernel 4: out = sum_r agg[r] @ W[r] + bias  (fp16 mma, K=1024 accumulated)
//   CTA = 64 out-rows; loops r with persistent fp32 accumulators,
//   double-buffered B via cp.async. 8 warps (2x4 tiling of 32x32),
//   2 CTAs/SM. ONE epilogue, no REDs.
// ---------------------------------------------------------------------------
__global__ void __launch_bounds__(256, 2)
gemm_mma_kernel(float* __restrict__ out, const float* __restrict__ bias) {
    extern __shared__ char smem[];
    const int m0 = blockIdx.x * MT;
    const int tid = threadIdx.x;
    const int wid = tid >> 5;
    const int lid = tid & 31;
    const uint32_t sb = smem_u32(smem);

    // prefetch B for rel 0 into buf 0
    {
#pragma unroll
        for (int i = 0; i < 8; i++) {
            int cid = tid + i * 256;      // 2048 chunks
            int row = cid >> 4;
            int chunk = cid & 15;
            cp16(sb + SM_B + sw_off(row, chunk), g_wt + (row << 7) + (chunk << 3));
        }
        CP_COMMIT();
    }

    // per-lane ldmatrix addresses
    const int wm = wid & 1;          // 2 m-tiles of 32 rows
    const int wn = wid >> 1;         // 4 n-tiles of 32 cols
    const int a_row = wm * 32 + (lid & 15);
    const int a_kc  = lid >> 4;
    const int a_and = a_row & 7;
    const uint32_t a_base = sb + (uint32_t)(a_row * 256);
    const int b_row = wn * 32 + ((lid >> 4) << 3) + (lid & 7);
    const int b_kc  = (lid >> 3) & 1;
    const int b_and = b_row & 7;
    const uint32_t b_row_off = (uint32_t)(b_row * 256);

    float acc[2][4][4];
#pragma unroll
    for (int mt = 0; mt < 2; mt++)
#pragma unroll
        for (int nn = 0; nn < 4; nn++)
#pragma unroll
            for (int c = 0; c < 4; c++) acc[mt][nn][c] = 0.0f;

#pragma unroll 1
    for (int r = 0; r < N_RELS; r++) {
        if (r > 0) __syncthreads();   // prev MMA done; A + next B buffer reusable

        // fill A from agg[r, m0:m0+64, :] (pure uint4 copies)
#pragma unroll
        for (int i = 0; i < 4; i++) {
            int cid = tid + i * 256;      // 1024 chunks
            int row = cid >> 4;
            int chunk = cid & 15;
            int grow = m0 + row;
            if (grow >= N_NODES) grow = 0;    // junk rows; epilogue guards
            *(uint4*)(smem + SM_A + sw_off(row, chunk)) =
                *(const uint4*)(g_agg + (((size_t)r * N_NODES + grow) << 7) + (chunk << 3));
        }

        // prefetch B for rel r+1 into the other buffer
        if (r + 1 < N_RELS) {
            const __half* Bn = g_wt + ((r + 1) << 14);
            const uint32_t nbuf = sb + SM_B + (uint32_t)((r + 1) & 1) * 32768;
#pragma unroll
            for (int i = 0; i < 8; i++) {
                int cid = tid + i * 256;
                int row = cid >> 4;
                int chunk = cid & 15;
                cp16(nbuf + sw_off(row, chunk), Bn + (row << 7) + (chunk << 3));
            }
            CP_COMMIT();
            CP_WAIT(1);    // B_r complete
        } else {
            CP_WAIT(0);
        }
        __syncthreads();

        const uint32_t bbuf = sb + SM_B + (uint32_t)(r & 1) * 32768;
#pragma unroll
        for (int s = 0; s < 8; s++) {
            uint32_t Ah[2][4], Bh4[2][4];
            const uint32_t ac = (uint32_t)(((s * 2 + a_kc) ^ a_and) << 4);
            const uint32_t bc = (uint32_t)(((s * 2 + b_kc) ^ b_and) << 4);
#pragma unroll
            for (int t2 = 0; t2 < 2; t2++) {
                ldsm4(Ah[t2], a_base + SM_A + t2 * 4096 + ac);
                ldsm4(Bh4[t2], bbuf + b_row_off + t2 * 4096 + bc);
            }
#pragma unroll
            for (int g = 0; g < 2; g++) {
#pragma unroll
                for (int half = 0; half < 2; half++) {
                    const int nn = g * 2 + half;
                    const uint32_t* bh = &Bh4[g][half * 2];
#pragma unroll
                    for (int mt = 0; mt < 2; mt++)
                        mma_fp16(acc[mt][nn], Ah[mt], bh);
                }
            }
        }
    }

    // ---- single epilogue: out = acc + bias ----
    const int col0 = wn * 32 + (lid & 3) * 2;
    float2 bb[4];
#pragma unroll
    for (int nn = 0; nn < 4; nn++)
        bb[nn] = make_float2(__ldg(bias + col0 + nn * 8), __ldg(bias + col0 + nn * 8 + 1));
    const int row_lo = m0 + wm * 32 + (lid >> 2);
#pragma unroll
    for (int mt = 0; mt < 2; mt++) {
        int row = row_lo + mt * 16;
        if (row < N_NODES) {
            float* Op = out + ((size_t)row << 7) + col0;
#pragma unroll
            for (int nn = 0; nn < 4; nn++)
                *(float2*)(Op + nn * 8) = make_float2(acc[mt][nn][0] + bb[nn].x,
                                                      acc[mt][nn][1] + bb[nn].y);
        }
        if (row + 8 < N_NODES) {
            float* Op = out + ((size_t)(row + 8) << 7) + col0;
#pragma unroll
            for (int nn = 0; nn < 4; nn++)
                *(float2*)(Op + nn * 8) = make_float2(acc[mt][nn][2] + bb[nn].x,
                                                      acc[mt][nn][3] + bb[nn].y);
        }
    }
}

// ---------------------------------------------------------------------------
extern "C" void kernel_launch(void* const* d_in, const int* in_sizes, int n_in,
                              void* d_out, int out_size) {
    const int*   triples  = (const int*)d_in[0];    // [E, 3] (src, rel, tgt)
    const float* features = (const float*)d_in[1];  // [N, 128]
    const float* weights  = (const float*)d_in[2];  // [8, 128, 128]
    const float* bias     = (const float*)d_in[3];  // [128]
    float* out = (float*)d_out;                     // [N, 128]
    (void)in_sizes; (void)n_in; (void)out_size;

    cudaFuncSetAttribute(gemm_mma_kernel,
                         cudaFuncAttributeMaxDynamicSharedMemorySize, SMEM_TOTAL);

    init_kernel<<<2048, 256>>>();
    count_kernel<<<(N_EDGES + 255) / 256, 256>>>(triples);
    split_w_kernel<<<(N_RELS * 128 * 128 + 255) / 256, 256>>>(weights);
    conv_a_kernel<<<(N_NODES * IN_DIM / 8 + 255) / 256, 256>>>(features);

    // 4 edges per thread, 8 threads per edge-quad
    scatter_kernel<<<(N_EDGES / 4 * 8 + 511) / 512, 512>>>(triples);

    gemm_mma_kernel<<<M_TILES, 256, SMEM_TOTAL>>>(out, bias);
}